// round 16
// baseline (speedup 1.0000x reference)
#include <cuda_runtime.h>
#include <cuda_fp16.h>
#include <cstdint>

// Problem constants
#define T_STEPS 100
#define BATCH   64
#define M_DIM   (T_STEPS * BATCH)   // 6400
#define N_DIM   1024
#define K_DIM   1024
#define KP      (K_DIM / 2)         // 512 packed fp16x2 per row
#define THR     15.0f

// scratch
__device__ float    g_delta[(size_t)M_DIM * N_DIM];     // 26 MB
__device__ uint32_t g_Apk [(size_t)M_DIM * KP];         // spikes as fp16x2, 13 MB
__device__ uint32_t g_Wh  [(size_t)N_DIM * KP];         // W hi (fp16x2), 2 MB
__device__ uint32_t g_Wl  [(size_t)N_DIM * KP];         // W lo residual (fp16x2)

// ---------------------------------------------------------------------------
// Prep: exact 2-way fp16 split of W (w = h + l, residual <= 2^-22 |w|),
// spikes -> fp16 (exact: values are {0,1}).
// ---------------------------------------------------------------------------
__device__ __forceinline__ uint32_t pack_h16(__half lo, __half hi) {
    return (uint32_t)__half_as_ushort(lo) | ((uint32_t)__half_as_ushort(hi) << 16);
}

__global__ void pack_a_kernel(const float* __restrict__ A) {
    int i = blockIdx.x * blockDim.x + threadIdx.x;      // pair index
    float2 v = *(const float2*)(A + (size_t)i * 2);
    g_Apk[i] = pack_h16(__float2half_rn(v.x), __float2half_rn(v.y));
}

__global__ void pack_w_kernel(const float* __restrict__ W) {
    int i = blockIdx.x * blockDim.x + threadIdx.x;      // pair index
    float2 v = *(const float2*)(W + (size_t)i * 2);
    __half h0 = __float2half_rn(v.x);
    __half l0 = __float2half_rn(v.x - __half2float(h0));   // w-h exact in fp32
    __half h1 = __float2half_rn(v.y);
    __half l1 = __float2half_rn(v.y - __half2float(h1));
    g_Wh[i] = pack_h16(h0, h1);
    g_Wl[i] = pack_h16(l0, l1);
}

// ---------------------------------------------------------------------------
// GEMM: g_delta = spikes @ W^T + b   via fp16 m16n8k16 tensor cores.
// Exact products (2-split fp16 W); chunked accumulation KC=32 (proven
// zero-flip). Same per-element arithmetic as the 133.6us kernel.
// NEW: CTA tile 128x64 (800 CTAs) at occupancy 2 to kill the 11% wave-
// quantization tail; cp.async double-buffered smem (no staging registers).
// 256 threads, 8 warps (4 along M x 2 along N), warp tile 32x32.
// ---------------------------------------------------------------------------
#define BM 128
#define BN 64
#define BK 32
#define BKP (BK / 2)        // 16 u32 per row per k-tile
#define STRU 20             // u32 row stride (16 + 4 pad) — ldsm conflict-free
#define RB   (STRU * 4)     // 80 bytes per row
#define AS_B (BM * RB)      // 10240 B
#define BS_B (BN * RB)      // 5120 B per plane
#define STAGE_B (AS_B + 2 * BS_B)   // 20480 B
#define SMEM_BYTES (2 * STAGE_B)    // 40960 B
#define NKT (K_DIM / BK)    // 32

__device__ __forceinline__ void mma_f16(float c[4], const uint32_t a[4], const uint32_t b[2]) {
    asm volatile(
        "mma.sync.aligned.m16n8k16.row.col.f32.f16.f16.f32 "
        "{%0,%1,%2,%3}, {%4,%5,%6,%7}, {%8,%9}, {%0,%1,%2,%3};\n"
        : "+f"(c[0]), "+f"(c[1]), "+f"(c[2]), "+f"(c[3])
        : "r"(a[0]), "r"(a[1]), "r"(a[2]), "r"(a[3]),
          "r"(b[0]), "r"(b[1]));
}

// D = A*B + 0  (fresh accumulator, no zeroing MOVs)
__device__ __forceinline__ void mma_f16_zc(float d[4], const uint32_t a[4], const uint32_t b[2]) {
    asm volatile(
        "mma.sync.aligned.m16n8k16.row.col.f32.f16.f16.f32 "
        "{%0,%1,%2,%3}, {%4,%5,%6,%7}, {%8,%9}, {%10,%10,%10,%10};\n"
        : "=f"(d[0]), "=f"(d[1]), "=f"(d[2]), "=f"(d[3])
        : "r"(a[0]), "r"(a[1]), "r"(a[2]), "r"(a[3]),
          "r"(b[0]), "r"(b[1]), "f"(0.0f));
}

__device__ __forceinline__ void ldsm_x4(uint32_t d[4], uint32_t saddr) {
    asm volatile(
        "ldmatrix.sync.aligned.m8n8.x4.shared.b16 {%0,%1,%2,%3}, [%4];\n"
        : "=r"(d[0]), "=r"(d[1]), "=r"(d[2]), "=r"(d[3])
        : "r"(saddr));
}

__device__ __forceinline__ uint32_t smem_u32(const void* p) {
    uint32_t a;
    asm("{ .reg .u64 t; cvta.to.shared.u64 t, %1; cvt.u32.u64 %0, t; }"
        : "=r"(a) : "l"(p));
    return a;
}

__global__ __launch_bounds__(256, 2) void gemm_tc_kernel(const float* __restrict__ bias)
{
    extern __shared__ char smem[];
    const uint32_t sbase = smem_u32(smem);

    const int tid  = threadIdx.x;
    const int m0   = blockIdx.y * BM;
    const int n0   = blockIdx.x * BN;

    const int lane = tid & 31;
    const int warp = tid >> 5;
    const int warp_m = (warp & 3) * 32;   // 4 warps along M
    const int warp_n = (warp >> 2) * 32;  // 2 warps along N
    const int g    = lane >> 2;           // 0..7
    const int t    = lane & 3;            // 0..3

    const int lrow16 = lane & 15;
    const int khalf  = (lane >> 4) * 16;  // bytes

    float acc[2][4][4];                   // TC chunk accumulator (one k-tile)
    float sum[2][4][4];                   // IEEE running sum
#pragma unroll
    for (int i = 0; i < 2; i++)
#pragma unroll
        for (int j = 0; j < 4; j++)
#pragma unroll
            for (int r = 0; r < 4; r++) sum[i][j][r] = 0.0f;

    // cp.async fill mapping: 1024 segs of 16B per stage; 4 segs per thread.
    //   seg < 512  -> As:  row = seg>>2 (0..127), 16B piece (seg&3)
    //   seg >= 512 -> W:   idx = seg-512; plane = idx>>8; row = (idx>>2)&63
    auto issue = [&](int kt, int buf) {
        const uint32_t s0 = sbase + (uint32_t)buf * STAGE_B;
        const int koff = kt * BKP;    // u32 offset in K of this tile
#pragma unroll
        for (int r = 0; r < 4; r++) {
            int seg = tid + r * 256;
            const uint32_t* gp;
            uint32_t sp;
            if (seg < 512) {
                int row = seg >> 2;
                int c4  = (seg & 3) * 4;
                gp = g_Apk + (size_t)(m0 + row) * KP + koff + c4;
                sp = s0 + (uint32_t)row * RB + (uint32_t)(seg & 3) * 16;
            } else {
                int idx = seg - 512;
                int pl  = idx >> 8;               // 0 = hi, 1 = lo
                int row = (idx >> 2) & 63;
                int c4  = (idx & 3) * 4;
                gp = (pl ? g_Wl : g_Wh) + (size_t)(n0 + row) * KP + koff + c4;
                sp = s0 + AS_B + (uint32_t)pl * BS_B
                        + (uint32_t)row * RB + (uint32_t)(idx & 3) * 16;
            }
            asm volatile("cp.async.cg.shared.global [%0], [%1], 16;\n"
                         :: "r"(sp), "l"(gp));
        }
        asm volatile("cp.async.commit_group;\n" ::: "memory");
    };

    issue(0, 0);

    for (int kt = 0; kt < NKT; kt++) {
        const int cur = kt & 1;
        asm volatile("cp.async.wait_group 0;\n" ::: "memory");
        __syncthreads();
        if (kt + 1 < NKT) issue(kt + 1, cur ^ 1);

        const uint32_t abase = sbase + (uint32_t)cur * STAGE_B;
        const uint32_t hbase = abase + AS_B;
        const uint32_t lbase = hbase + BS_B;

        // two K=16 steps per k-tile
#pragma unroll
        for (int kkp = 0; kkp < BKP; kkp += 8) {
            const uint32_t kbyte = kkp * 4 + khalf;

            uint32_t af[2][4];
#pragma unroll
            for (int i = 0; i < 2; i++) {
                uint32_t addr = abase + (uint32_t)(warp_m + i * 16 + lrow16) * RB + kbyte;
                ldsm_x4(af[i], addr);
            }

            uint32_t bf[2][4][2];   // [plane][n-frag][reg]
#pragma unroll
            for (int p = 0; p < 2; p++) {    // n-frag pairs (frags 2p, 2p+1)
                uint32_t nrow = (uint32_t)(warp_n + p * 16 + lrow16) * RB + kbyte;
                uint32_t d0[4], d1[4];
                ldsm_x4(d0, hbase + nrow);
                ldsm_x4(d1, lbase + nrow);
                bf[0][2 * p    ][0] = d0[0];  bf[0][2 * p    ][1] = d0[2];
                bf[0][2 * p + 1][0] = d0[1];  bf[0][2 * p + 1][1] = d0[3];
                bf[1][2 * p    ][0] = d1[0];  bf[1][2 * p    ][1] = d1[2];
                bf[1][2 * p + 1][0] = d1[1];  bf[1][2 * p + 1][1] = d1[3];
            }

            if (kkp == 0) {
                // first k-step of the chunk: hi-plane mma writes acc fresh (C=0)
#pragma unroll
                for (int i = 0; i < 2; i++)
#pragma unroll
                    for (int j = 0; j < 4; j++)
                        mma_f16_zc(acc[i][j], af[i], bf[0][j]);
#pragma unroll
                for (int i = 0; i < 2; i++)
#pragma unroll
                    for (int j = 0; j < 4; j++)
                        mma_f16(acc[i][j], af[i], bf[1][j]);
            } else {
#pragma unroll
                for (int s = 0; s < 2; s++)
#pragma unroll
                    for (int i = 0; i < 2; i++)
#pragma unroll
                        for (int j = 0; j < 4; j++)
                            mma_f16(acc[i][j], af[i], bf[s][j]);
            }
        }

        // flush EVERY k-tile (KC = 32, proven zero-flip): IEEE RN adds only
#pragma unroll
        for (int i = 0; i < 2; i++)
#pragma unroll
            for (int j = 0; j < 4; j++)
#pragma unroll
                for (int r = 0; r < 4; r++)
                    sum[i][j][r] += acc[i][j][r];
        __syncthreads();
    }

    // epilogue: + bias (single fp32 add), float2 stores
#pragma unroll
    for (int i = 0; i < 2; i++) {
        int row0 = m0 + warp_m + i * 16 + g;
#pragma unroll
        for (int j = 0; j < 4; j++) {
            int col = n0 + warp_n + j * 8 + t * 2;
            float b0 = __ldg(bias + col);
            float b1 = __ldg(bias + col + 1);
            float2 lo = make_float2(sum[i][j][0] + b0, sum[i][j][1] + b1);
            float2 hi = make_float2(sum[i][j][2] + b0, sum[i][j][3] + b1);
            *(float2*)(g_delta + (size_t)row0       * N_DIM + col) = lo;
            *(float2*)(g_delta + (size_t)(row0 + 8) * N_DIM + col) = hi;
        }
    }
}

// ---------------- Scan over T: scalar per element, batched loads ------------
// out layout: [ ss (T*B*N) | mem_out (B*N) | hat_s (B*N) ]  all fp32
__global__ void scan_kernel(const float* __restrict__ mem_in,
                            float* __restrict__ out)
{
    const int j = blockIdx.x * blockDim.x + threadIdx.x;   // 0 .. 65535
    const int BN_ELEMS = BATCH * N_DIM;                    // 65536

    float m = mem_in[j];
    float ssum = 0.0f;

    for (int t0 = 0; t0 < T_STEPS; t0 += 20) {
        float buf[20];
#pragma unroll
        for (int u = 0; u < 20; u++)            // MLP = 20 loads in flight
            buf[u] = g_delta[(size_t)(t0 + u) * BN_ELEMS + j];
#pragma unroll
        for (int u = 0; u < 20; u++) {
            m += buf[u];
            float s = (m > THR) ? 1.0f : 0.0f;
            m = fminf(fmaxf(m, 0.0f), THR);     // clip(0, thr)
            m = m - m * s;                      // reset fired neurons
            out[(size_t)(t0 + u) * BN_ELEMS + j] = s;
            ssum += s;                          // integer-valued, exact
        }
    }

    const size_t ss_total = (size_t)T_STEPS * BN_ELEMS;
    out[ss_total + j]            = m;                      // mem_out
    out[ss_total + BN_ELEMS + j] = ssum / (float)T_STEPS;  // hat_s
}

// ---------------------------------------------------------------------------
extern "C" void kernel_launch(void* const* d_in, const int* in_sizes, int n_in,
                              void* d_out, int out_size)
{
    const float* spikes = (const float*)d_in[0];   // [100,64,1024]
    const float* mem    = (const float*)d_in[1];   // [64,1024]
    // d_in[2] = hat_spikes: numerically dead in the forward pass
    const float* W      = (const float*)d_in[3];   // [1024,1024]
    const float* b      = (const float*)d_in[4];   // [1024]
    float* out          = (float*)d_out;

    pack_a_kernel<<<(M_DIM * KP) / 256, 256>>>(spikes);
    pack_w_kernel<<<(N_DIM * KP) / 256, 256>>>(W);

    cudaFuncSetAttribute(gemm_tc_kernel,
                         cudaFuncAttributeMaxDynamicSharedMemorySize, SMEM_BYTES);
    dim3 grid(N_DIM / BN, M_DIM / BM);   // (16, 50) = 800 CTAs
    gemm_tc_kernel<<<grid, 256, SMEM_BYTES>>>(b);

    scan_kernel<<<(BATCH * N_DIM) / 256, 256>>>(mem, out);
}